// round 2
// baseline (speedup 1.0000x reference)
#include <cuda_runtime.h>
#include <cuda_bf16.h>

#define N_NODES 50000
#define N_EDGES 800000
#define XD 128
#define HD 256
#define YD 128

// Scratch (module-load-time allocation; legal per harness rules)
__device__ float g_xn[(size_t)N_NODES * XD];  // normalized x
__device__ float g_ax[(size_t)N_NODES * XD];  // A @ xn
__device__ float g_h [(size_t)N_NODES * HD];  // relu(ax @ W1 + b1)
__device__ float g_ah[(size_t)N_NODES * HD];  // A @ h

// ---------------------------------------------------------------------------
// Zero the two scatter-destination buffers (d_out is poisoned; g_* persist
// across graph replays so they must be re-zeroed every launch).
// ---------------------------------------------------------------------------
__global__ __launch_bounds__(256) void zero_accum_kernel() {
    size_t i = (size_t)blockIdx.x * blockDim.x + threadIdx.x;
    const size_t n_ax4 = (size_t)N_NODES * XD / 4;
    const size_t n_ah4 = (size_t)N_NODES * HD / 4;
    float4 z = make_float4(0.f, 0.f, 0.f, 0.f);
    if (i < n_ax4) {
        reinterpret_cast<float4*>(g_ax)[i] = z;
    } else if (i < n_ax4 + n_ah4) {
        reinterpret_cast<float4*>(g_ah)[i - n_ax4] = z;
    }
}

// ---------------------------------------------------------------------------
// Row-normalize: xn[i,:] = x[i,:] / (sum_j x[i,j] + 1e-4). One warp per row.
// ---------------------------------------------------------------------------
__global__ __launch_bounds__(256) void norm_rows_kernel(const float* __restrict__ x) {
    int row  = (blockIdx.x * blockDim.x + threadIdx.x) >> 5;
    int lane = threadIdx.x & 31;
    if (row >= N_NODES) return;
    const float4* xr = reinterpret_cast<const float4*>(x + (size_t)row * XD);
    float4 v = xr[lane];
    float s = v.x + v.y + v.z + v.w;
    #pragma unroll
    for (int o = 16; o > 0; o >>= 1) s += __shfl_xor_sync(0xFFFFFFFFu, s, o);
    float inv = 1.0f / (s + 1e-4f);
    v.x *= inv; v.y *= inv; v.z *= inv; v.w *= inv;
    reinterpret_cast<float4*>(g_xn + (size_t)row * XD)[lane] = v;
}

// ---------------------------------------------------------------------------
// SpMM via gather + vectorized global reduction. One warp per edge.
// dst[row,:] += val * src[col,:]
// ---------------------------------------------------------------------------
__device__ __forceinline__ void red_add_v4(float* p, float4 m) {
    asm volatile("red.global.add.v4.f32 [%0], {%1,%2,%3,%4};"
                 :: "l"(p), "f"(m.x), "f"(m.y), "f"(m.z), "f"(m.w)
                 : "memory");
}

template <int D>
__global__ __launch_bounds__(256) void spmm_kernel(
    const float* __restrict__ vals,
    const int*   __restrict__ rows,
    const int*   __restrict__ cols,
    const float* __restrict__ src,
    float*       __restrict__ dst)
{
    int e    = (blockIdx.x * blockDim.x + threadIdx.x) >> 5;
    int lane = threadIdx.x & 31;
    if (e >= N_EDGES) return;
    float v = vals[e];
    int   r = rows[e];
    int   c = cols[e];
    const float4* s4 = reinterpret_cast<const float4*>(src + (size_t)c * D);
    float* drow = dst + (size_t)r * D;
    #pragma unroll
    for (int i = 0; i < D / 128; i++) {
        float4 m = s4[lane + 32 * i];
        m.x *= v; m.y *= v; m.z *= v; m.w *= v;
        red_add_v4(drow + (lane + 32 * i) * 4, m);
    }
}

// ---------------------------------------------------------------------------
// GEMM 1: h = relu(g_ax[50000,128] @ W1[128,256] + b1). Block = 256 threads,
// 32 rows per block, one output column per thread, A-tile in smem.
// ---------------------------------------------------------------------------
__global__ __launch_bounds__(256) void gemm1_relu_kernel(
    const float* __restrict__ A,   // g_ax
    const float* __restrict__ W,   // [128,256]
    const float* __restrict__ b,   // [256]
    float*       __restrict__ out) // g_h [50000,256]
{
    __shared__ float sA[32 * 128];
    int j    = threadIdx.x;            // 0..255 output column
    int row0 = blockIdx.x * 32;
    int nrows = N_NODES - row0; if (nrows > 32) nrows = 32;

    const float4* a4 = reinterpret_cast<const float4*>(A + (size_t)row0 * 128);
    float4* s4 = reinterpret_cast<float4*>(sA);
    for (int i = threadIdx.x; i < nrows * 32; i += 256) s4[i] = a4[i];
    __syncthreads();

    float acc[32];
    #pragma unroll
    for (int r = 0; r < 32; r++) acc[r] = 0.f;

    for (int k = 0; k < 128; k++) {
        float w = W[k * 256 + j];
        #pragma unroll
        for (int r = 0; r < 32; r++) acc[r] += sA[r * 128 + k] * w;
    }
    float bj = b[j];
    for (int r = 0; r < nrows; r++)
        out[(size_t)(row0 + r) * 256 + j] = fmaxf(acc[r] + bj, 0.f);
}

// ---------------------------------------------------------------------------
// GEMM 2: y = g_ah[50000,256] @ W2[256,128] + b2. Block = 128 threads,
// 32 rows per block, one output column per thread.
// ---------------------------------------------------------------------------
__global__ __launch_bounds__(128) void gemm2_kernel(
    const float* __restrict__ A,   // g_ah
    const float* __restrict__ W,   // [256,128]
    const float* __restrict__ b,   // [128]
    float*       __restrict__ out) // d_out [50000,128]
{
    __shared__ float sA[32 * 256];
    int j    = threadIdx.x;            // 0..127 output column
    int row0 = blockIdx.x * 32;
    int nrows = N_NODES - row0; if (nrows > 32) nrows = 32;

    const float4* a4 = reinterpret_cast<const float4*>(A + (size_t)row0 * 256);
    float4* s4 = reinterpret_cast<float4*>(sA);
    for (int i = threadIdx.x; i < nrows * 64; i += 128) s4[i] = a4[i];
    __syncthreads();

    float acc[32];
    #pragma unroll
    for (int r = 0; r < 32; r++) acc[r] = 0.f;

    for (int k = 0; k < 256; k++) {
        float w = W[k * 128 + j];
        #pragma unroll
        for (int r = 0; r < 32; r++) acc[r] += sA[r * 256 + k] * w;
    }
    float bj = b[j];
    for (int r = 0; r < nrows; r++)
        out[(size_t)(row0 + r) * 128 + j] = acc[r] + bj;
}

// ---------------------------------------------------------------------------
extern "C" void kernel_launch(void* const* d_in, const int* in_sizes, int n_in,
                              void* d_out, int out_size) {
    const float* x        = (const float*)d_in[0];
    const float* adj_vals = (const float*)d_in[1];
    const int*   adj_row  = (const int*)  d_in[2];
    const int*   adj_col  = (const int*)  d_in[3];
    const float* W1       = (const float*)d_in[4];
    const float* b1       = (const float*)d_in[5];
    const float* W2       = (const float*)d_in[6];
    const float* b2       = (const float*)d_in[7];
    float* y = (float*)d_out;

    float *xn, *ax, *h, *ah;
    cudaGetSymbolAddress((void**)&xn, g_xn);
    cudaGetSymbolAddress((void**)&ax, g_ax);
    cudaGetSymbolAddress((void**)&h,  g_h);
    cudaGetSymbolAddress((void**)&ah, g_ah);

    // zero accumulation buffers (ax + ah), float4 granularity
    {
        size_t n4 = ((size_t)N_NODES * XD + (size_t)N_NODES * HD) / 4;
        int grid = (int)((n4 + 255) / 256);
        zero_accum_kernel<<<grid, 256>>>();
    }
    // row-normalize x -> g_xn
    {
        int grid = (N_NODES * 32 + 255) / 256;
        norm_rows_kernel<<<grid, 256>>>(x);
    }
    // spmm1: g_ax = A @ g_xn
    {
        int grid = (N_EDGES + 7) / 8;   // 8 warps (edges) per 256-thread block
        spmm_kernel<128><<<grid, 256>>>(adj_vals, adj_row, adj_col, xn, ax);
    }
    // gemm1: g_h = relu(g_ax @ W1 + b1)
    {
        int grid = (N_NODES + 31) / 32;
        gemm1_relu_kernel<<<grid, 256>>>(ax, W1, b1, h);
    }
    // spmm2: g_ah = A @ g_h
    {
        int grid = (N_EDGES + 7) / 8;
        spmm_kernel<256><<<grid, 256>>>(adj_vals, adj_row, adj_col, h, ah);
    }
    // gemm2: y = g_ah @ W2 + b2
    {
        int grid = (N_NODES + 31) / 32;
        gemm2_kernel<<<grid, 128>>>(ah, W2, b2, y);
    }
}

// round 3
// speedup vs baseline: 1.8788x; 1.8788x over previous
#include <cuda_runtime.h>
#include <cuda_bf16.h>

#define N_NODES 50000
#define N_EDGES 800000
#define XD 128
#define HD 256
#define YD 128

// Scratch buffers (static device allocations; legal per harness rules)
__device__ float g_xn[(size_t)N_NODES * XD];  // normalized x; later reused as t = h@W2
__device__ float g_ax[(size_t)N_NODES * XD];  // A @ xn
__device__ float g_h [(size_t)N_NODES * HD];  // relu(ax @ W1 + b1)

// ---------------------------------------------------------------------------
// Init: zero g_ax (scatter dest 1) and fill d_out with broadcast b2
// (scatter dest 2 accumulates on top of the bias -> final answer directly).
// ---------------------------------------------------------------------------
__global__ __launch_bounds__(256) void init_kernel(const float* __restrict__ b2,
                                                   float* __restrict__ out) {
    size_t i = (size_t)blockIdx.x * blockDim.x + threadIdx.x;
    const size_t n4 = (size_t)N_NODES * XD / 4;   // 1.6M float4 each
    if (i < n4) {
        reinterpret_cast<float4*>(g_ax)[i] = make_float4(0.f, 0.f, 0.f, 0.f);
    } else if (i < 2 * n4) {
        size_t j = i - n4;
        float4 bv = reinterpret_cast<const float4*>(b2)[j & 31];  // 128/4 = 32 chunks
        reinterpret_cast<float4*>(out)[j] = bv;
    }
}

// ---------------------------------------------------------------------------
// Row-normalize: xn[i,:] = x[i,:] / (sum_j x[i,j] + 1e-4). One warp per row.
// ---------------------------------------------------------------------------
__global__ __launch_bounds__(256) void norm_rows_kernel(const float* __restrict__ x) {
    int row  = (blockIdx.x * blockDim.x + threadIdx.x) >> 5;
    int lane = threadIdx.x & 31;
    if (row >= N_NODES) return;
    const float4* xr = reinterpret_cast<const float4*>(x + (size_t)row * XD);
    float4 v = xr[lane];
    float s = v.x + v.y + v.z + v.w;
    #pragma unroll
    for (int o = 16; o > 0; o >>= 1) s += __shfl_xor_sync(0xFFFFFFFFu, s, o);
    float inv = 1.0f / (s + 1e-4f);
    v.x *= inv; v.y *= inv; v.z *= inv; v.w *= inv;
    reinterpret_cast<float4*>(g_xn + (size_t)row * XD)[lane] = v;
}

// ---------------------------------------------------------------------------
// SpMM via gather + vectorized global reduction. One warp per edge, D=128.
// dst[row,:] += val * src[col,:]
// ---------------------------------------------------------------------------
__device__ __forceinline__ void red_add_v4(float* p, float4 m) {
    asm volatile("red.global.add.v4.f32 [%0], {%1,%2,%3,%4};"
                 :: "l"(p), "f"(m.x), "f"(m.y), "f"(m.z), "f"(m.w)
                 : "memory");
}

__global__ __launch_bounds__(256) void spmm128_kernel(
    const float* __restrict__ vals,
    const int*   __restrict__ rows,
    const int*   __restrict__ cols,
    const float* __restrict__ src,
    float*       __restrict__ dst)
{
    int e    = (blockIdx.x * blockDim.x + threadIdx.x) >> 5;
    int lane = threadIdx.x & 31;
    if (e >= N_EDGES) return;
    float v = vals[e];
    int   r = rows[e];
    int   c = cols[e];
    float4 m = reinterpret_cast<const float4*>(src + (size_t)c * 128)[lane];
    m.x *= v; m.y *= v; m.z *= v; m.w *= v;
    red_add_v4(dst + (size_t)r * 128 + lane * 4, m);
}

// ---------------------------------------------------------------------------
// Register-tiled SGEMM with packed f32x2 FMA.
// out[M,N] = op(A[M,K] @ W[K,N] + bias)   op = relu or identity
// Block tile 128x128, 256 threads, 8x8 per thread, BK=16.
// ---------------------------------------------------------------------------
__device__ __forceinline__ unsigned long long pack_dup(float x) {
    unsigned long long r;
    unsigned int xi = __float_as_uint(x);
    asm("mov.b64 %0, {%1, %1};" : "=l"(r) : "r"(xi));
    return r;
}
__device__ __forceinline__ unsigned long long fma2(unsigned long long a,
                                                   unsigned long long b,
                                                   unsigned long long c) {
    unsigned long long d;
    asm("fma.rn.f32x2 %0, %1, %2, %3;" : "=l"(d) : "l"(a), "l"(b), "l"(c));
    return d;
}

template<int N_DIM, int K_DIM, bool RELU, bool HAS_BIAS>
__global__ __launch_bounds__(256) void gemm_kernel(
    const float* __restrict__ A,
    const float* __restrict__ W,
    const float* __restrict__ bias,
    float*       __restrict__ out,
    int M)
{
    constexpr int BM = 128, BN = 128, BK = 16;
    constexpr int LDA = 132, LDW = 132;  // padded to dodge bank conflicts
    __shared__ float As[BK * LDA];       // As[k][m]  (A transposed)
    __shared__ float Ws[BK * LDW];       // Ws[k][n]

    const int tid = threadIdx.x;
    const int tx  = tid & 15;            // 0..15 -> 8 cols each
    const int ty  = tid >> 4;            // 0..15 -> 8 rows each
    const int row0 = blockIdx.x * BM;
    const int col0 = blockIdx.y * BN;

    // A-load mapping: thread loads 2 rows (r, r+64), one float4 k-chunk each
    const int a_r  = tid >> 2;           // 0..63
    const int a_c4 = (tid & 3) * 4;      // k offset within BK: 0,4,8,12
    // W-load mapping: thread loads row kk, two float4 col-chunks
    const int w_kk = tid >> 4;           // 0..15
    const int w_c  = (tid & 15) * 4;     // 0..60

    unsigned long long acc[8][4];
    #pragma unroll
    for (int i = 0; i < 8; i++)
        #pragma unroll
        for (int j = 0; j < 4; j++) acc[i][j] = 0ULL;

    for (int k0 = 0; k0 < K_DIM; k0 += BK) {
        // ---- load A tile (transposed into As) ----
        #pragma unroll
        for (int half = 0; half < 2; half++) {
            int r  = a_r + half * 64;
            int gr = row0 + r; if (gr >= M) gr = M - 1;   // clamp (stores guarded)
            float4 v = *reinterpret_cast<const float4*>(A + (size_t)gr * K_DIM + k0 + a_c4);
            As[(a_c4 + 0) * LDA + r] = v.x;
            As[(a_c4 + 1) * LDA + r] = v.y;
            As[(a_c4 + 2) * LDA + r] = v.z;
            As[(a_c4 + 3) * LDA + r] = v.w;
        }
        // ---- load W tile ----
        #pragma unroll
        for (int half = 0; half < 2; half++) {
            int c = w_c + half * 64;
            float4 v = *reinterpret_cast<const float4*>(W + (size_t)(k0 + w_kk) * N_DIM + col0 + c);
            *reinterpret_cast<float4*>(&Ws[w_kk * LDW + c]) = v;
        }
        __syncthreads();

        // ---- compute ----
        #pragma unroll
        for (int kk = 0; kk < BK; kk++) {
            const float* as = &As[kk * LDA + ty * 8];
            float4 a0 = *reinterpret_cast<const float4*>(as);
            float4 a1 = *reinterpret_cast<const float4*>(as + 4);
            const unsigned long long* wp =
                reinterpret_cast<const unsigned long long*>(&Ws[kk * LDW + tx * 8]);
            unsigned long long w0 = wp[0], w1 = wp[1], w2 = wp[2], w3 = wp[3];
            float a[8] = {a0.x, a0.y, a0.z, a0.w, a1.x, a1.y, a1.z, a1.w};
            #pragma unroll
            for (int i = 0; i < 8; i++) {
                unsigned long long ad = pack_dup(a[i]);
                acc[i][0] = fma2(ad, w0, acc[i][0]);
                acc[i][1] = fma2(ad, w1, acc[i][1]);
                acc[i][2] = fma2(ad, w2, acc[i][2]);
                acc[i][3] = fma2(ad, w3, acc[i][3]);
            }
        }
        __syncthreads();
    }

    // ---- epilogue ----
    float bv[8];
    #pragma unroll
    for (int j = 0; j < 8; j++)
        bv[j] = HAS_BIAS ? bias[col0 + tx * 8 + j] : 0.f;

    #pragma unroll
    for (int i = 0; i < 8; i++) {
        int m = row0 + ty * 8 + i;
        if (m >= M) break;
        float r[8];
        #pragma unroll
        for (int j = 0; j < 4; j++) {
            float2 p = *reinterpret_cast<float2*>(&acc[i][j]);
            r[2 * j]     = p.x + bv[2 * j];
            r[2 * j + 1] = p.y + bv[2 * j + 1];
        }
        if (RELU) {
            #pragma unroll
            for (int j = 0; j < 8; j++) r[j] = fmaxf(r[j], 0.f);
        }
        float* orow = out + (size_t)m * N_DIM + col0 + tx * 8;
        *reinterpret_cast<float4*>(orow)     = make_float4(r[0], r[1], r[2], r[3]);
        *reinterpret_cast<float4*>(orow + 4) = make_float4(r[4], r[5], r[6], r[7]);
    }
}

// ---------------------------------------------------------------------------
extern "C" void kernel_launch(void* const* d_in, const int* in_sizes, int n_in,
                              void* d_out, int out_size) {
    const float* x        = (const float*)d_in[0];
    const float* adj_vals = (const float*)d_in[1];
    const int*   adj_row  = (const int*)  d_in[2];
    const int*   adj_col  = (const int*)  d_in[3];
    const float* W1       = (const float*)d_in[4];
    const float* b1       = (const float*)d_in[5];
    const float* W2       = (const float*)d_in[6];
    const float* b2       = (const float*)d_in[7];
    float* y = (float*)d_out;

    float *xn, *ax, *h;
    cudaGetSymbolAddress((void**)&xn, g_xn);
    cudaGetSymbolAddress((void**)&ax, g_ax);
    cudaGetSymbolAddress((void**)&h,  g_h);
    float* t = xn;  // reuse g_xn for t = h @ W2 after spmm1 consumed it

    // 1) init: zero g_ax, fill d_out with broadcast b2
    {
        size_t n4 = 2 * ((size_t)N_NODES * XD / 4);
        init_kernel<<<(int)((n4 + 255) / 256), 256>>>(b2, y);
    }
    // 2) row-normalize x -> g_xn
    norm_rows_kernel<<<(N_NODES * 32 + 255) / 256, 256>>>(x);
    // 3) spmm1: g_ax += A @ g_xn   (D=128)
    spmm128_kernel<<<(N_EDGES + 7) / 8, 256>>>(adj_vals, adj_row, adj_col, xn, ax);
    // 4) gemm1: g_h = relu(g_ax @ W1 + b1)   [50000x256], K=128
    {
        dim3 grid((N_NODES + 127) / 128, HD / 128);
        gemm_kernel<HD, XD, true, true><<<grid, 256>>>(ax, W1, b1, h, N_NODES);
    }
    // 5) gemm2: t = g_h @ W2   [50000x128], K=256 (bias folded into d_out init)
    {
        dim3 grid((N_NODES + 127) / 128, YD / 128);
        gemm_kernel<YD, HD, false, false><<<grid, 256>>>(h, W2, nullptr, t, N_NODES);
    }
    // 6) spmm2: d_out += A @ t   (D=128) -> final y (bias pre-filled)
    spmm128_kernel<<<(N_EDGES + 7) / 8, 256>>>(adj_vals, adj_row, adj_col, t, y);
}

// round 4
// speedup vs baseline: 1.8895x; 1.0057x over previous
#include <cuda_runtime.h>
#include <cuda_bf16.h>

#define N_NODES 50000
#define N_EDGES 800000
#define XD 128
#define HD 256
#define YD 128

// Scratch buffers (static device allocations; legal per harness rules)
__device__ float g_xn[(size_t)N_NODES * XD];  // normalized x; later reused as t = h@W2
__device__ float g_ax[(size_t)N_NODES * XD];  // A @ xn
__device__ float g_h [(size_t)N_NODES * HD];  // relu(ax @ W1 + b1)

// ---------------------------------------------------------------------------
// Init: zero g_ax (scatter dest 1) and fill d_out with broadcast b2
// (scatter dest 2 accumulates on top of the bias -> final answer directly).
// ---------------------------------------------------------------------------
__global__ __launch_bounds__(256) void init_kernel(const float* __restrict__ b2,
                                                   float* __restrict__ out) {
    size_t i = (size_t)blockIdx.x * blockDim.x + threadIdx.x;
    const size_t n4 = (size_t)N_NODES * XD / 4;   // 1.6M float4 each
    if (i < n4) {
        reinterpret_cast<float4*>(g_ax)[i] = make_float4(0.f, 0.f, 0.f, 0.f);
    } else if (i < 2 * n4) {
        size_t j = i - n4;
        float4 bv = reinterpret_cast<const float4*>(b2)[j & 31];  // 128/4 = 32 chunks
        reinterpret_cast<float4*>(out)[j] = bv;
    }
}

// ---------------------------------------------------------------------------
// Row-normalize: xn[i,:] = x[i,:] / (sum_j x[i,j] + 1e-4). One warp per row.
// ---------------------------------------------------------------------------
__global__ __launch_bounds__(256) void norm_rows_kernel(const float* __restrict__ x) {
    int row  = (blockIdx.x * blockDim.x + threadIdx.x) >> 5;
    int lane = threadIdx.x & 31;
    if (row >= N_NODES) return;
    const float4* xr = reinterpret_cast<const float4*>(x + (size_t)row * XD);
    float4 v = xr[lane];
    float s = v.x + v.y + v.z + v.w;
    #pragma unroll
    for (int o = 16; o > 0; o >>= 1) s += __shfl_xor_sync(0xFFFFFFFFu, s, o);
    float inv = 1.0f / (s + 1e-4f);
    v.x *= inv; v.y *= inv; v.z *= inv; v.w *= inv;
    reinterpret_cast<float4*>(g_xn + (size_t)row * XD)[lane] = v;
}

// ---------------------------------------------------------------------------
// SpMM via gather + vectorized global reduction. One warp per edge, D=128.
// dst[row,:] += val * src[col,:]
// ---------------------------------------------------------------------------
__device__ __forceinline__ void red_add_v4(float* p, float4 m) {
    asm volatile("red.global.add.v4.f32 [%0], {%1,%2,%3,%4};"
                 :: "l"(p), "f"(m.x), "f"(m.y), "f"(m.z), "f"(m.w)
                 : "memory");
}

__global__ __launch_bounds__(256) void spmm128_kernel(
    const float* __restrict__ vals,
    const int*   __restrict__ rows,
    const int*   __restrict__ cols,
    const float* __restrict__ src,
    float*       __restrict__ dst)
{
    int e    = (blockIdx.x * blockDim.x + threadIdx.x) >> 5;
    int lane = threadIdx.x & 31;
    if (e >= N_EDGES) return;
    float v = vals[e];
    int   r = rows[e];
    int   c = cols[e];
    float4 m = reinterpret_cast<const float4*>(src + (size_t)c * 128)[lane];
    m.x *= v; m.y *= v; m.z *= v; m.w *= v;
    red_add_v4(dst + (size_t)r * 128 + lane * 4, m);
}

// ---------------------------------------------------------------------------
// Register-tiled SGEMM with packed f32x2 FMA.
// out[M,N] = op(A[M,K] @ W[K,N] + bias)   op = relu or identity
// Block tile 128x128, 256 threads, 8x8 per thread, BK=16.
// ---------------------------------------------------------------------------
__device__ __forceinline__ unsigned long long pack_dup(float x) {
    unsigned long long r;
    unsigned int xi = __float_as_uint(x);
    asm("mov.b64 %0, {%1, %1};" : "=l"(r) : "r"(xi));
    return r;
}
__device__ __forceinline__ unsigned long long fma2(unsigned long long a,
                                                   unsigned long long b,
                                                   unsigned long long c) {
    unsigned long long d;
    asm("fma.rn.f32x2 %0, %1, %2, %3;" : "=l"(d) : "l"(a), "l"(b), "l"(c));
    return d;
}

template<int N_DIM, int K_DIM, bool RELU, bool HAS_BIAS>
__global__ __launch_bounds__(256) void gemm_kernel(
    const float* __restrict__ A,
    const float* __restrict__ W,
    const float* __restrict__ bias,
    float*       __restrict__ out,
    int M)
{
    constexpr int BM = 128, BN = 128, BK = 16;
    constexpr int LDA = 132, LDW = 132;  // padded to dodge bank conflicts
    __shared__ float As[BK * LDA];       // As[k][m]  (A transposed)
    __shared__ float Ws[BK * LDW];       // Ws[k][n]

    const int tid = threadIdx.x;
    const int tx  = tid & 15;            // 0..15 -> 8 cols each
    const int ty  = tid >> 4;            // 0..15 -> 8 rows each
    const int row0 = blockIdx.x * BM;
    const int col0 = blockIdx.y * BN;

    // A-load mapping: thread loads 2 rows (r, r+64), one float4 k-chunk each
    const int a_r  = tid >> 2;           // 0..63
    const int a_c4 = (tid & 3) * 4;      // k offset within BK: 0,4,8,12
    // W-load mapping: thread loads row kk, two float4 col-chunks
    const int w_kk = tid >> 4;           // 0..15
    const int w_c  = (tid & 15) * 4;     // 0..60

    unsigned long long acc[8][4];
    #pragma unroll
    for (int i = 0; i < 8; i++)
        #pragma unroll
        for (int j = 0; j < 4; j++) acc[i][j] = 0ULL;

    for (int k0 = 0; k0 < K_DIM; k0 += BK) {
        // ---- load A tile (transposed into As) ----
        #pragma unroll
        for (int half = 0; half < 2; half++) {
            int r  = a_r + half * 64;
            int gr = row0 + r; if (gr >= M) gr = M - 1;   // clamp (stores guarded)
            float4 v = *reinterpret_cast<const float4*>(A + (size_t)gr * K_DIM + k0 + a_c4);
            As[(a_c4 + 0) * LDA + r] = v.x;
            As[(a_c4 + 1) * LDA + r] = v.y;
            As[(a_c4 + 2) * LDA + r] = v.z;
            As[(a_c4 + 3) * LDA + r] = v.w;
        }
        // ---- load W tile ----
        #pragma unroll
        for (int half = 0; half < 2; half++) {
            int c = w_c + half * 64;
            float4 v = *reinterpret_cast<const float4*>(W + (size_t)(k0 + w_kk) * N_DIM + col0 + c);
            *reinterpret_cast<float4*>(&Ws[w_kk * LDW + c]) = v;
        }
        __syncthreads();

        // ---- compute ----
        #pragma unroll
        for (int kk = 0; kk < BK; kk++) {
            const float* as = &As[kk * LDA + ty * 8];
            float4 a0 = *reinterpret_cast<const float4*>(as);
            float4 a1 = *reinterpret_cast<const float4*>(as + 4);
            const unsigned long long* wp =
                reinterpret_cast<const unsigned long long*>(&Ws[kk * LDW + tx * 8]);
            unsigned long long w0 = wp[0], w1 = wp[1], w2 = wp[2], w3 = wp[3];
            float a[8] = {a0.x, a0.y, a0.z, a0.w, a1.x, a1.y, a1.z, a1.w};
            #pragma unroll
            for (int i = 0; i < 8; i++) {
                unsigned long long ad = pack_dup(a[i]);
                acc[i][0] = fma2(ad, w0, acc[i][0]);
                acc[i][1] = fma2(ad, w1, acc[i][1]);
                acc[i][2] = fma2(ad, w2, acc[i][2]);
                acc[i][3] = fma2(ad, w3, acc[i][3]);
            }
        }
        __syncthreads();
    }

    // ---- epilogue ----
    float bv[8];
    #pragma unroll
    for (int j = 0; j < 8; j++)
        bv[j] = HAS_BIAS ? bias[col0 + tx * 8 + j] : 0.f;

    #pragma unroll
    for (int i = 0; i < 8; i++) {
        int m = row0 + ty * 8 + i;
        if (m >= M) break;
        float r[8];
        #pragma unroll
        for (int j = 0; j < 4; j++) {
            float2 p = *reinterpret_cast<float2*>(&acc[i][j]);
            r[2 * j]     = p.x + bv[2 * j];
            r[2 * j + 1] = p.y + bv[2 * j + 1];
        }
        if (RELU) {
            #pragma unroll
            for (int j = 0; j < 8; j++) r[j] = fmaxf(r[j], 0.f);
        }
        float* orow = out + (size_t)m * N_DIM + col0 + tx * 8;
        *reinterpret_cast<float4*>(orow)     = make_float4(r[0], r[1], r[2], r[3]);
        *reinterpret_cast<float4*>(orow + 4) = make_float4(r[4], r[5], r[6], r[7]);
    }
}

// ---------------------------------------------------------------------------
extern "C" void kernel_launch(void* const* d_in, const int* in_sizes, int n_in,
                              void* d_out, int out_size) {
    const float* x        = (const float*)d_in[0];
    const float* adj_vals = (const float*)d_in[1];
    const int*   adj_row  = (const int*)  d_in[2];
    const int*   adj_col  = (const int*)  d_in[3];
    const float* W1       = (const float*)d_in[4];
    const float* b1       = (const float*)d_in[5];
    const float* W2       = (const float*)d_in[6];
    const float* b2       = (const float*)d_in[7];
    float* y = (float*)d_out;

    float *xn, *ax, *h;
    cudaGetSymbolAddress((void**)&xn, g_xn);
    cudaGetSymbolAddress((void**)&ax, g_ax);
    cudaGetSymbolAddress((void**)&h,  g_h);
    float* t = xn;  // reuse g_xn for t = h @ W2 after spmm1 consumed it

    // 1) init: zero g_ax, fill d_out with broadcast b2
    {
        size_t n4 = 2 * ((size_t)N_NODES * XD / 4);
        init_kernel<<<(int)((n4 + 255) / 256), 256>>>(b2, y);
    }
    // 2) row-normalize x -> g_xn
    norm_rows_kernel<<<(N_NODES * 32 + 255) / 256, 256>>>(x);
    // 3) spmm1: g_ax += A @ g_xn   (D=128)
    spmm128_kernel<<<(N_EDGES + 7) / 8, 256>>>(adj_vals, adj_row, adj_col, xn, ax);
    // 4) gemm1: g_h = relu(g_ax @ W1 + b1)   [50000x256], K=128
    {
        dim3 grid((N_NODES + 127) / 128, HD / 128);
        gemm_kernel<HD, XD, true, true><<<grid, 256>>>(ax, W1, b1, h, N_NODES);
    }
    // 5) gemm2: t = g_h @ W2   [50000x128], K=256 (bias folded into d_out init)
    {
        dim3 grid((N_NODES + 127) / 128, YD / 128);
        gemm_kernel<YD, HD, false, false><<<grid, 256>>>(h, W2, nullptr, t, N_NODES);
    }
    // 6) spmm2: d_out += A @ t   (D=128) -> final y (bias pre-filled)
    spmm128_kernel<<<(N_EDGES + 7) / 8, 256>>>(adj_vals, adj_row, adj_col, t, y);
}

// round 5
// speedup vs baseline: 2.0608x; 1.0906x over previous
#include <cuda_runtime.h>
#include <cuda_bf16.h>

#define N_NODES 50000
#define N_EDGES 800000
#define XD 128
#define HD 256
#define YD 128

// Scratch buffers (static device allocations; legal per harness rules)
__device__ float g_xn[(size_t)N_NODES * XD];  // normalized x; later reused as t = h@W2
__device__ float g_ax[(size_t)N_NODES * XD];  // A @ xn
__device__ float g_h [(size_t)N_NODES * HD];  // relu(ax @ W1 + b1)

// CSR scratch (rebuilt every launch — deterministic work)
__device__ int   g_cnt   [N_NODES];
__device__ int   g_rowptr[N_NODES + 1];
__device__ int   g_cursor[N_NODES];
__device__ float g_cval  [N_EDGES];
__device__ int   g_ccol  [N_EDGES];

// ---------------------------------------------------------------------------
// CSR build step 1: zero per-row counts
// ---------------------------------------------------------------------------
__global__ __launch_bounds__(256) void csr_zero_kernel() {
    int i = blockIdx.x * blockDim.x + threadIdx.x;
    if (i < N_NODES) g_cnt[i] = 0;
}

// CSR build step 2: histogram of row indices
__global__ __launch_bounds__(256) void csr_hist_kernel(const int* __restrict__ rows) {
    int e = blockIdx.x * blockDim.x + threadIdx.x;
    if (e < N_EDGES) atomicAdd(&g_cnt[rows[e]], 1);
}

// CSR build step 3: exclusive scan (single block, 1024 threads, 49 elems each)
__global__ __launch_bounds__(1024) void csr_scan_kernel() {
    __shared__ int s[1024];
    const int t = threadIdx.x;
    const int CHUNK = (N_NODES + 1023) / 1024;   // 49
    const int base = t * CHUNK;

    int local = 0;
    for (int i = 0; i < CHUNK; i++) {
        int idx = base + i;
        if (idx < N_NODES) local += g_cnt[idx];
    }
    s[t] = local;
    __syncthreads();
    // Hillis-Steele inclusive scan
    #pragma unroll
    for (int off = 1; off < 1024; off <<= 1) {
        int v = (t >= off) ? s[t - off] : 0;
        __syncthreads();
        s[t] += v;
        __syncthreads();
    }
    int pre = (t == 0) ? 0 : s[t - 1];   // exclusive prefix of this chunk
    for (int i = 0; i < CHUNK; i++) {
        int idx = base + i;
        if (idx < N_NODES) {
            g_rowptr[idx] = pre;
            g_cursor[idx] = pre;
            pre += g_cnt[idx];
        }
    }
    if (t == 1023) g_rowptr[N_NODES] = s[1023];
}

// CSR build step 4: scatter edges into CSR order
__global__ __launch_bounds__(256) void csr_scatter_kernel(
    const float* __restrict__ vals,
    const int*   __restrict__ rows,
    const int*   __restrict__ cols)
{
    int e = blockIdx.x * blockDim.x + threadIdx.x;
    if (e >= N_EDGES) return;
    int r = rows[e];
    int pos = atomicAdd(&g_cursor[r], 1);
    g_cval[pos] = vals[e];
    g_ccol[pos] = cols[e];
}

// ---------------------------------------------------------------------------
// Row-normalize: xn[i,:] = x[i,:] / (sum_j x[i,j] + 1e-4). One warp per row.
// ---------------------------------------------------------------------------
__global__ __launch_bounds__(256) void norm_rows_kernel(const float* __restrict__ x) {
    int row  = (blockIdx.x * blockDim.x + threadIdx.x) >> 5;
    int lane = threadIdx.x & 31;
    if (row >= N_NODES) return;
    const float4* xr = reinterpret_cast<const float4*>(x + (size_t)row * XD);
    float4 v = xr[lane];
    float s = v.x + v.y + v.z + v.w;
    #pragma unroll
    for (int o = 16; o > 0; o >>= 1) s += __shfl_xor_sync(0xFFFFFFFFu, s, o);
    float inv = 1.0f / (s + 1e-4f);
    v.x *= inv; v.y *= inv; v.z *= inv; v.w *= inv;
    reinterpret_cast<float4*>(g_xn + (size_t)row * XD)[lane] = v;
}

// ---------------------------------------------------------------------------
// CSR SpMM, D=128: one warp per output row, float4 accumulators in registers.
// dst[row,:] = (bias?) + sum_e val_e * src[col_e,:]
// ---------------------------------------------------------------------------
template<bool HAS_BIAS>
__global__ __launch_bounds__(256) void spmm_csr128_kernel(
    const float* __restrict__ src,
    const float* __restrict__ bias,
    float*       __restrict__ dst)
{
    int row  = (blockIdx.x * blockDim.x + threadIdx.x) >> 5;
    int lane = threadIdx.x & 31;
    if (row >= N_NODES) return;

    int s = g_rowptr[row];
    int e = g_rowptr[row + 1];

    float4 acc;
    if (HAS_BIAS) acc = reinterpret_cast<const float4*>(bias)[lane];
    else          acc = make_float4(0.f, 0.f, 0.f, 0.f);

    const float4* src4 = reinterpret_cast<const float4*>(src);

    int i = s;
    for (; i + 2 <= e; i += 2) {
        float v0 = __ldg(&g_cval[i]);
        float v1 = __ldg(&g_cval[i + 1]);
        int   c0 = __ldg(&g_ccol[i]);
        int   c1 = __ldg(&g_ccol[i + 1]);
        float4 m0 = src4[(size_t)c0 * 32 + lane];
        float4 m1 = src4[(size_t)c1 * 32 + lane];
        acc.x = fmaf(v0, m0.x, acc.x); acc.y = fmaf(v0, m0.y, acc.y);
        acc.z = fmaf(v0, m0.z, acc.z); acc.w = fmaf(v0, m0.w, acc.w);
        acc.x = fmaf(v1, m1.x, acc.x); acc.y = fmaf(v1, m1.y, acc.y);
        acc.z = fmaf(v1, m1.z, acc.z); acc.w = fmaf(v1, m1.w, acc.w);
    }
    if (i < e) {
        float v0 = __ldg(&g_cval[i]);
        int   c0 = __ldg(&g_ccol[i]);
        float4 m0 = src4[(size_t)c0 * 32 + lane];
        acc.x = fmaf(v0, m0.x, acc.x); acc.y = fmaf(v0, m0.y, acc.y);
        acc.z = fmaf(v0, m0.z, acc.z); acc.w = fmaf(v0, m0.w, acc.w);
    }
    reinterpret_cast<float4*>(dst)[(size_t)row * 32 + lane] = acc;
}

// ---------------------------------------------------------------------------
// Register-tiled SGEMM with packed f32x2 FMA (unchanged from R4).
// ---------------------------------------------------------------------------
__device__ __forceinline__ unsigned long long pack_dup(float x) {
    unsigned long long r;
    unsigned int xi = __float_as_uint(x);
    asm("mov.b64 %0, {%1, %1};" : "=l"(r) : "r"(xi));
    return r;
}
__device__ __forceinline__ unsigned long long fma2(unsigned long long a,
                                                   unsigned long long b,
                                                   unsigned long long c) {
    unsigned long long d;
    asm("fma.rn.f32x2 %0, %1, %2, %3;" : "=l"(d) : "l"(a), "l"(b), "l"(c));
    return d;
}

template<int N_DIM, int K_DIM, bool RELU, bool HAS_BIAS>
__global__ __launch_bounds__(256) void gemm_kernel(
    const float* __restrict__ A,
    const float* __restrict__ W,
    const float* __restrict__ bias,
    float*       __restrict__ out,
    int M)
{
    constexpr int BM = 128, BN = 128, BK = 16;
    constexpr int LDA = 132, LDW = 132;
    __shared__ float As[BK * LDA];       // As[k][m]  (A transposed)
    __shared__ float Ws[BK * LDW];       // Ws[k][n]

    const int tid = threadIdx.x;
    const int tx  = tid & 15;
    const int ty  = tid >> 4;
    const int row0 = blockIdx.x * BM;
    const int col0 = blockIdx.y * BN;

    const int a_r  = tid >> 2;
    const int a_c4 = (tid & 3) * 4;
    const int w_kk = tid >> 4;
    const int w_c  = (tid & 15) * 4;

    unsigned long long acc[8][4];
    #pragma unroll
    for (int i = 0; i < 8; i++)
        #pragma unroll
        for (int j = 0; j < 4; j++) acc[i][j] = 0ULL;

    for (int k0 = 0; k0 < K_DIM; k0 += BK) {
        #pragma unroll
        for (int half = 0; half < 2; half++) {
            int r  = a_r + half * 64;
            int gr = row0 + r; if (gr >= M) gr = M - 1;
            float4 v = *reinterpret_cast<const float4*>(A + (size_t)gr * K_DIM + k0 + a_c4);
            As[(a_c4 + 0) * LDA + r] = v.x;
            As[(a_c4 + 1) * LDA + r] = v.y;
            As[(a_c4 + 2) * LDA + r] = v.z;
            As[(a_c4 + 3) * LDA + r] = v.w;
        }
        #pragma unroll
        for (int half = 0; half < 2; half++) {
            int c = w_c + half * 64;
            float4 v = *reinterpret_cast<const float4*>(W + (size_t)(k0 + w_kk) * N_DIM + col0 + c);
            *reinterpret_cast<float4*>(&Ws[w_kk * LDW + c]) = v;
        }
        __syncthreads();

        #pragma unroll
        for (int kk = 0; kk < BK; kk++) {
            const float* as = &As[kk * LDA + ty * 8];
            float4 a0 = *reinterpret_cast<const float4*>(as);
            float4 a1 = *reinterpret_cast<const float4*>(as + 4);
            const unsigned long long* wp =
                reinterpret_cast<const unsigned long long*>(&Ws[kk * LDW + tx * 8]);
            unsigned long long w0 = wp[0], w1 = wp[1], w2 = wp[2], w3 = wp[3];
            float a[8] = {a0.x, a0.y, a0.z, a0.w, a1.x, a1.y, a1.z, a1.w};
            #pragma unroll
            for (int i = 0; i < 8; i++) {
                unsigned long long ad = pack_dup(a[i]);
                acc[i][0] = fma2(ad, w0, acc[i][0]);
                acc[i][1] = fma2(ad, w1, acc[i][1]);
                acc[i][2] = fma2(ad, w2, acc[i][2]);
                acc[i][3] = fma2(ad, w3, acc[i][3]);
            }
        }
        __syncthreads();
    }

    float bv[8];
    #pragma unroll
    for (int j = 0; j < 8; j++)
        bv[j] = HAS_BIAS ? bias[col0 + tx * 8 + j] : 0.f;

    #pragma unroll
    for (int i = 0; i < 8; i++) {
        int m = row0 + ty * 8 + i;
        if (m >= M) break;
        float r[8];
        #pragma unroll
        for (int j = 0; j < 4; j++) {
            float2 p = *reinterpret_cast<float2*>(&acc[i][j]);
            r[2 * j]     = p.x + bv[2 * j];
            r[2 * j + 1] = p.y + bv[2 * j + 1];
        }
        if (RELU) {
            #pragma unroll
            for (int j = 0; j < 8; j++) r[j] = fmaxf(r[j], 0.f);
        }
        float* orow = out + (size_t)m * N_DIM + col0 + tx * 8;
        *reinterpret_cast<float4*>(orow)     = make_float4(r[0], r[1], r[2], r[3]);
        *reinterpret_cast<float4*>(orow + 4) = make_float4(r[4], r[5], r[6], r[7]);
    }
}

// ---------------------------------------------------------------------------
extern "C" void kernel_launch(void* const* d_in, const int* in_sizes, int n_in,
                              void* d_out, int out_size) {
    const float* x        = (const float*)d_in[0];
    const float* adj_vals = (const float*)d_in[1];
    const int*   adj_row  = (const int*)  d_in[2];
    const int*   adj_col  = (const int*)  d_in[3];
    const float* W1       = (const float*)d_in[4];
    const float* b1       = (const float*)d_in[5];
    const float* W2       = (const float*)d_in[6];
    const float* b2       = (const float*)d_in[7];
    float* y = (float*)d_out;

    float *xn, *ax, *h;
    cudaGetSymbolAddress((void**)&xn, g_xn);
    cudaGetSymbolAddress((void**)&ax, g_ax);
    cudaGetSymbolAddress((void**)&h,  g_h);
    float* t = xn;  // reuse g_xn for t = h @ W2 after spmm1 consumed it

    // --- CSR build (shared by both SpMMs) ---
    csr_zero_kernel<<<(N_NODES + 255) / 256, 256>>>();
    csr_hist_kernel<<<(N_EDGES + 255) / 256, 256>>>(adj_row);
    csr_scan_kernel<<<1, 1024>>>();
    csr_scatter_kernel<<<(N_EDGES + 255) / 256, 256>>>(adj_vals, adj_row, adj_col);

    // --- row-normalize x -> g_xn (overlaps nothing; cheap) ---
    norm_rows_kernel<<<(N_NODES * 32 + 255) / 256, 256>>>(x);

    // --- spmm1: g_ax = A @ g_xn (D=128, no bias) ---
    spmm_csr128_kernel<false><<<(N_NODES * 32 + 255) / 256, 256>>>(xn, nullptr, ax);

    // --- gemm1: g_h = relu(g_ax @ W1 + b1) ---
    {
        dim3 grid((N_NODES + 127) / 128, HD / 128);
        gemm_kernel<HD, XD, true, true><<<grid, 256>>>(ax, W1, b1, h, N_NODES);
    }
    // --- gemm2: t = g_h @ W2 (bias folded into spmm2) ---
    {
        dim3 grid((N_NODES + 127) / 128, YD / 128);
        gemm_kernel<YD, HD, false, false><<<grid, 256>>>(h, W2, nullptr, t, N_NODES);
    }
    // --- spmm2: y = b2 + A @ t (D=128) ---
    spmm_csr128_kernel<true><<<(N_NODES * 32 + 255) / 256, 256>>>(t, b2, y);
}